// round 5
// baseline (speedup 1.0000x reference)
#include <cuda_runtime.h>
#include <cuda_bf16.h>
#include <math.h>

// AUCM pairwise margin loss, B=1024 rows, C=128 classes, margin=1.
//
// Key identity: sum over (pos i, neg j) pairs of softplus(b_j - a_i) where
// a,b in (0,1) (sigmoid outputs) so t = b-a in (-1,1). On that interval
//   softplus(t) = t/2 + ln2 + u^2/2 - u^4/12 + u^6/45 - 17 u^8/2520 + O(u^10),
//   u = t/2, truncation error <= 2.2e-6 absolute.
// Polynomial in (b-a) factorizes over the pair sum via the binomial theorem
// into products of power sums, so the O(B^2) pair loop per class reduces to
// 9 power-sum moments of pos probs and 9 of neg probs -> O(B*C) work total.

#define NROWS 1024
#define NCLS  128
#define NTHREADS 256
#define ROWS_PER_THREAD (NROWS / NTHREADS)

__device__ float g_per_class[NCLS];
__device__ float g_valid[NCLS];

__global__ __launch_bounds__(NTHREADS)
void aucm_class_kernel(const float* __restrict__ logits,
                       const float* __restrict__ targets)
{
    const int c   = blockIdx.x;   // class index
    const int tid = threadIdx.x;

    // Power-sum moments: A[k] = sum over pos rows of p^k, B[k] = same for neg.
    float A[9];
    float Bm[9];
#pragma unroll
    for (int k = 0; k < 9; k++) { A[k] = 0.0f; Bm[k] = 0.0f; }

#pragma unroll
    for (int r = 0; r < ROWS_PER_THREAD; r++) {
        const int   row = tid + r * NTHREADS;
        const float x   = logits[row * NCLS + c];
        const float tgt = targets[row * NCLS + c];
        const float p   = __fdividef(1.0f, 1.0f + __expf(-x));  // sigmoid
        float pw = 1.0f;
        if (tgt > 0.5f) {
#pragma unroll
            for (int k = 0; k < 9; k++) { A[k] += pw; pw *= p; }
        } else {
#pragma unroll
            for (int k = 0; k < 9; k++) { Bm[k] += pw; pw *= p; }
        }
    }

    // Warp tree reduction of the 18 accumulators.
#pragma unroll
    for (int off = 16; off > 0; off >>= 1) {
#pragma unroll
        for (int k = 0; k < 9; k++) {
            A[k]  += __shfl_xor_sync(0xffffffffu, A[k],  off);
            Bm[k] += __shfl_xor_sync(0xffffffffu, Bm[k], off);
        }
    }

    __shared__ float sA[NTHREADS / 32][9];
    __shared__ float sB[NTHREADS / 32][9];
    const int warp = tid >> 5;
    const int lane = tid & 31;
    if (lane == 0) {
#pragma unroll
        for (int k = 0; k < 9; k++) { sA[warp][k] = A[k]; sB[warp][k] = Bm[k]; }
    }
    __syncthreads();

    if (tid == 0) {
        // Cross-warp reduce + binomial combination in fp64 (cancellation-safe;
        // only ~100 DFMA per class, negligible cost).
        double Ad[9], Bd[9];
#pragma unroll
        for (int k = 0; k < 9; k++) {
            double sa = 0.0, sb = 0.0;
            for (int w = 0; w < NTHREADS / 32; w++) { sa += (double)sA[w][k]; sb += (double)sB[w][k]; }
            Ad[k] = sa; Bd[k] = sb;
        }
        // Am[k] = sum over pos of (-a)^k
        double Am[9];
#pragma unroll
        for (int k = 0; k < 9; k++) Am[k] = (k & 1) ? -Ad[k] : Ad[k];

        const double np  = Ad[0];
        const double nn  = Bd[0];
        const double cnt = np * nn;

        // d_m = sum_{pairs} (b - a)^m = sum_r C(m,r) * Bd[r] * Am[m-r]
        const double C2[3] = {1, 2, 1};
        const double C4[5] = {1, 4, 6, 4, 1};
        const double C6[7] = {1, 6, 15, 20, 15, 6, 1};
        const double C8[9] = {1, 8, 28, 56, 70, 56, 28, 8, 1};

        const double d1 = Bd[1] * Am[0] + Bd[0] * Am[1];
        double d2 = 0.0, d4 = 0.0, d6 = 0.0, d8 = 0.0;
#pragma unroll
        for (int r = 0; r <= 2; r++) d2 += C2[r] * Bd[r] * Am[2 - r];
#pragma unroll
        for (int r = 0; r <= 4; r++) d4 += C4[r] * Bd[r] * Am[4 - r];
#pragma unroll
        for (int r = 0; r <= 6; r++) d6 += C6[r] * Bd[r] * Am[6 - r];
#pragma unroll
        for (int r = 0; r <= 8; r++) d8 += C8[r] * Bd[r] * Am[8 - r];

        // softplus(t) = t/2 + ln2 + t^2/8 - t^4/192 + t^6/2880 - 17 t^8/645120
        const double S = 0.5 * d1
                       + 0.6931471805599453 * cnt
                       + d2 * (1.0 / 8.0)
                       - d4 * (1.0 / 192.0)
                       + d6 * (1.0 / 2880.0)
                       - d8 * (17.0 / 645120.0);

        const bool valid = (cnt > 0.0);
        g_per_class[c] = valid ? (float)(S / cnt) : 0.0f;
        g_valid[c]     = valid ? 1.0f : 0.0f;
    }
}

__global__ __launch_bounds__(NCLS)
void aucm_finalize_kernel(float* __restrict__ out)
{
    __shared__ double s[NCLS];
    __shared__ double sv[NCLS];
    const int tid = threadIdx.x;
    s[tid]  = (double)g_per_class[tid];
    sv[tid] = (double)g_valid[tid];
    __syncthreads();
#pragma unroll
    for (int off = NCLS / 2; off > 0; off >>= 1) {
        if (tid < off) { s[tid] += s[tid + off]; sv[tid] += sv[tid + off]; }
        __syncthreads();
    }
    if (tid == 0) {
        out[0] = (sv[0] > 0.0) ? (float)(s[0] / sv[0]) : 0.0f;
    }
}

extern "C" void kernel_launch(void* const* d_in, const int* in_sizes, int n_in,
                              void* d_out, int out_size)
{
    const float* logits  = (const float*)d_in[0];
    const float* targets = (const float*)d_in[1];
    float* out = (float*)d_out;

    aucm_class_kernel<<<NCLS, NTHREADS>>>(logits, targets);
    aucm_finalize_kernel<<<1, NCLS>>>(out);
}

// round 6
// speedup vs baseline: 1.9791x; 1.9791x over previous
#include <cuda_runtime.h>
#include <cuda_bf16.h>
#include <math.h>

// AUCM pairwise margin loss, B=1024, C=128, margin=1. Single fused kernel.
//
// Factorization: sum over (pos i, neg j) of softplus(b_j - a_i), a,b = sigmoid
// outputs in (0,1) so t = b-a in (-1,1). Degree-6 expansion on that interval:
//   softplus(t) = ln2 + t/2 + t^2/8 - t^4/192 + t^6/2880   (+ 17 t^8/645120...)
// worst-case per-pair truncation 2.6e-5 abs; mean-level error ~1e-7 rel.
// (b-a)^m factorizes over the pair sum via the binomial theorem into products
// of power sums, so O(B^2) pairs collapse to 7 power-sum moments of pos probs
// and 7 of all probs (neg = all - pos since targets are exact {0,1}).
//
// One launch: 128 blocks (one per class) compute per-class means; the last
// block to finish (atomic ticket) reduces the 128 values to the scalar loss
// and resets the ticket counter so graph replays stay deterministic.

#define NROWS 1024
#define NCLS  128
#define NTH   256
#define RPT   (NROWS / NTH)   // 4 rows per thread
#define NM    7               // moments k = 0..6
#define NW    (NTH / 32)      // 8 warps

__device__ float g_pc[NCLS];          // per-class mean
__device__ float g_vd[NCLS];          // per-class validity
__device__ unsigned int g_count = 0;  // completion ticket

__global__ __launch_bounds__(NTH)
void aucm_fused_kernel(const float* __restrict__ logits,
                       const float* __restrict__ targets,
                       float* __restrict__ out)
{
    const int c    = blockIdx.x;   // class
    const int tid  = threadIdx.x;
    const int warp = tid >> 5;
    const int lane = tid & 31;

    // T[k] = sum over ALL rows of p^k, P[k] = sum over POS rows of p^k.
    float T[NM], P[NM];
#pragma unroll
    for (int k = 0; k < NM; k++) { T[k] = 0.0f; P[k] = 0.0f; }

#pragma unroll
    for (int r = 0; r < RPT; r++) {
        const int   row = tid + r * NTH;
        const float x   = logits[row * NCLS + c];
        const float tg  = targets[row * NCLS + c];   // exact 0.0f or 1.0f
        const float p   = __fdividef(1.0f, 1.0f + __expf(-x));
        float pw = 1.0f;
#pragma unroll
        for (int k = 0; k < NM; k++) {
            T[k] += pw;
            P[k] = fmaf(tg, pw, P[k]);
            pw *= p;
        }
    }

    // Warp tree reduction (14 accumulators).
#pragma unroll
    for (int off = 16; off > 0; off >>= 1) {
#pragma unroll
        for (int k = 0; k < NM; k++) {
            T[k] += __shfl_xor_sync(0xffffffffu, T[k], off);
            P[k] += __shfl_xor_sync(0xffffffffu, P[k], off);
        }
    }

    __shared__ float sT[NW][NM];
    __shared__ float sP[NW][NM];
    __shared__ unsigned int s_ticket;
    if (lane == 0) {
#pragma unroll
        for (int k = 0; k < NM; k++) { sT[warp][k] = T[k]; sP[warp][k] = P[k]; }
    }
    __syncthreads();

    if (tid == 0) {
        // Cross-warp sums, then binomial combine in fp64 (cancellation-safe,
        // ~30 DFMA once per class).
        double Td[NM], Pd[NM];
#pragma unroll
        for (int k = 0; k < NM; k++) {
            float a = 0.0f, b = 0.0f;
#pragma unroll
            for (int w = 0; w < NW; w++) { a += sT[w][k]; b += sP[w][k]; }
            Td[k] = (double)a; Pd[k] = (double)b;
        }
        double Bd[NM], Am[NM];
#pragma unroll
        for (int k = 0; k < NM; k++) {
            Bd[k] = Td[k] - Pd[k];                    // neg moments
            Am[k] = (k & 1) ? -Pd[k] : Pd[k];         // sum over pos of (-a)^k
        }
        const double cnt = Pd[0] * Bd[0];

        // d_m = sum_{pairs} (b-a)^m = sum_r C(m,r) * Bd[r] * Am[m-r]
        const double C2[3] = {1, 2, 1};
        const double C4[5] = {1, 4, 6, 4, 1};
        const double C6[7] = {1, 6, 15, 20, 15, 6, 1};

        const double d1 = Bd[1] * Am[0] + Bd[0] * Am[1];
        double d2 = 0.0, d4 = 0.0, d6 = 0.0;
#pragma unroll
        for (int r = 0; r <= 2; r++) d2 += C2[r] * Bd[r] * Am[2 - r];
#pragma unroll
        for (int r = 0; r <= 4; r++) d4 += C4[r] * Bd[r] * Am[4 - r];
#pragma unroll
        for (int r = 0; r <= 6; r++) d6 += C6[r] * Bd[r] * Am[6 - r];

        const double S = 0.6931471805599453 * cnt
                       + 0.5 * d1
                       + d2 * (1.0 / 8.0)
                       - d4 * (1.0 / 192.0)
                       + d6 * (1.0 / 2880.0);

        const bool valid = (cnt > 0.0);
        g_pc[c] = valid ? (float)(S / cnt) : 0.0f;
        g_vd[c] = valid ? 1.0f : 0.0f;

        __threadfence();                               // publish g_pc/g_vd
        s_ticket = atomicAdd(&g_count, 1u);
    }
    __syncthreads();

    // Last block to arrive does the final 128-way reduction.
    if (s_ticket == (unsigned)(NCLS - 1)) {
        __threadfence();   // acquire: see all other blocks' g_pc writes
        float v = 0.0f, vd = 0.0f;
        if (tid < NCLS) {
            // volatile loads: bypass any stale L1 state
            v  = *((volatile float*)&g_pc[tid]);
            vd = *((volatile float*)&g_vd[tid]);
        }
#pragma unroll
        for (int off = 16; off > 0; off >>= 1) {
            v  += __shfl_xor_sync(0xffffffffu, v,  off);
            vd += __shfl_xor_sync(0xffffffffu, vd, off);
        }
        __shared__ float fv[NW], fvd[NW];
        if (lane == 0) { fv[warp] = v; fvd[warp] = vd; }
        __syncthreads();
        if (tid == 0) {
            float sv = 0.0f, svd = 0.0f;
#pragma unroll
            for (int w = 0; w < NCLS / 32; w++) { sv += fv[w]; svd += fvd[w]; }
            out[0] = (svd > 0.0f) ? (sv / svd) : 0.0f;
            g_count = 0;   // reset for next graph replay (determinism)
        }
    }
}

extern "C" void kernel_launch(void* const* d_in, const int* in_sizes, int n_in,
                              void* d_out, int out_size)
{
    const float* logits  = (const float*)d_in[0];
    const float* targets = (const float*)d_in[1];
    float* out = (float*)d_out;

    aucm_fused_kernel<<<NCLS, NTH>>>(logits, targets, out);
}